// round 11
// baseline (speedup 1.0000x reference)
#include <cuda_runtime.h>
#include <cuda_fp16.h>
#include <cstdint>

#define NB  16
#define NC  256
#define NHW 4096

// ---------------- scratch ----------------------------------------------------
__device__ __half g_Wqkv[3 * NC * NC];
__device__ __half g_xT[(size_t)NB * NHW * NC];        // [b][n][c]
__device__ __half g_phi[(size_t)NB * 3 * NC * NHW];   // [b][q/-/v][c][n] (slot 1 unused)
__device__ __half g_phiKT[(size_t)NB * NHW * NC];     // [b][n][c]
__device__ float  g_qvp[4 * NB * NC * NC];            // split-K partials [ks][b][c][d]
__device__ __half g_M[NB * NC * NC];                  // [b][o][d], scaled by 1/16

// ---------------- helpers ---------------------------------------------------
__device__ __forceinline__ void mma16816(float* c, const uint32_t* a, const uint32_t* b) {
    asm volatile(
        "mma.sync.aligned.m16n8k16.row.col.f32.f16.f16.f32 "
        "{%0,%1,%2,%3},{%4,%5,%6,%7},{%8,%9},{%0,%1,%2,%3};\n"
        : "+f"(c[0]), "+f"(c[1]), "+f"(c[2]), "+f"(c[3])
        : "r"(a[0]), "r"(a[1]), "r"(a[2]), "r"(a[3]), "r"(b[0]), "r"(b[1]));
}
__device__ __forceinline__ float phi_f(float v) { return v > 0.0f ? v + 1.0f : __expf(v); }

__device__ __forceinline__ void cpa16(uint32_t s, const void* g) {
    asm volatile("cp.async.cg.shared.global [%0], [%1], 16;" :: "r"(s), "l"(g));
}
#define CPA_COMMIT() asm volatile("cp.async.commit_group;" ::: "memory")
#define CPA_WAIT0()  asm volatile("cp.async.wait_group 0;" ::: "memory")

#define LOAD_AFRAG(dst, S, r0, kk, P)                                   \
    do {                                                                \
        dst[0] = *(const uint32_t*)&S[(r0) * (P) + (kk)];               \
        dst[1] = *(const uint32_t*)&S[((r0) + 8) * (P) + (kk)];         \
        dst[2] = *(const uint32_t*)&S[(r0) * (P) + (kk) + 8];           \
        dst[3] = *(const uint32_t*)&S[((r0) + 8) * (P) + (kk) + 8];     \
    } while (0)
#define LOAD_BFRAG(dst, S, r0, kk, P)                                   \
    do {                                                                \
        dst[0] = *(const uint32_t*)&S[(r0) * (P) + (kk)];               \
        dst[1] = *(const uint32_t*)&S[(r0) * (P) + (kk) + 8];           \
    } while (0)

// ---------------- K0a: weight prep (fp16 QKV) --------------------------------
__global__ void prep_weights(const float* __restrict__ Wq, const float* __restrict__ Wk,
                             const float* __restrict__ Wv) {
    int i = blockIdx.x * blockDim.x + threadIdx.x;
    if (i < NC * NC) {
        g_Wqkv[i]               = __float2half_rn(Wq[i]);
        g_Wqkv[NC * NC + i]     = __float2half_rn(Wk[i]);
        g_Wqkv[2 * NC * NC + i] = __float2half_rn(Wv[i]);
    }
}

// ---------------- K0b: x[b][c][n] f32 -> g_xT[b][n][c] fp16 ------------------
__global__ void transpose_x(const float* __restrict__ x) {
    __shared__ float tile[32][33];
    int b = blockIdx.z, n0 = blockIdx.x * 32, c0 = blockIdx.y * 32;
    int tx = threadIdx.x, ty = threadIdx.y;
    const float* xb = x + (size_t)b * NC * NHW;
#pragma unroll
    for (int j = 0; j < 32; j += 8)
        tile[ty + j][tx] = xb[(size_t)(c0 + ty + j) * NHW + n0 + tx];
    __syncthreads();
    __half* o = g_xT + (size_t)b * NHW * NC;
#pragma unroll
    for (int j = 0; j < 32; j += 8)
        o[(size_t)(n0 + ty + j) * NC + c0 + tx] = __float2half_rn(tile[tx][ty + j]);
}

// ---------------- K1: QKV projection + phi (cp.async double-buffered) --------
__global__ __launch_bounds__(256) void proj_kernel() {
    __shared__ __align__(16) char raw[40960];
    const int b = blockIdx.z, mt = blockIdx.y, nt = blockIdx.x;
    const int t = threadIdx.x, warp = t >> 5, lane = t & 31;
    const int wm = (warp >> 1) * 32, wn = (warp & 1) * 64;
    const int fr = lane >> 2, fc = (lane & 3) * 2;
    const int lr = t >> 2, lc = (t & 3) * 8;

    float acc[2][8][4] = {};
    const __half* Ag = g_Wqkv + (size_t)(mt * 128) * NC;
    const __half* Bg = g_xT + ((size_t)b * NHW + nt * 128) * NC;
    uint32_t raw_s = (uint32_t)__cvta_generic_to_shared(raw);

    auto issue = [&](int s, int k0) {
        uint32_t base = raw_s + s * 20480;
#pragma unroll
        for (int i = 0; i < 2; i++) {
            int r = lr + i * 64;
            cpa16(base + (r * 40 + lc) * 2, Ag + (size_t)r * NC + k0 + lc);
            cpa16(base + 10240 + (r * 40 + lc) * 2, Bg + (size_t)r * NC + k0 + lc);
        }
    };

    issue(0, 0); CPA_COMMIT();
    for (int it = 0; it < 8; it++) {
        CPA_WAIT0();
        __syncthreads();
        if (it < 7) { issue((it + 1) & 1, (it + 1) * 32); CPA_COMMIT(); }
        const __half* sA = (const __half*)(raw + (it & 1) * 20480);
        const __half* sB = sA + 5120;
#pragma unroll
        for (int ks = 0; ks < 32; ks += 16) {
            uint32_t a[2][4];
            LOAD_AFRAG(a[0], sA, wm + fr, ks + fc, 40);
            LOAD_AFRAG(a[1], sA, wm + 16 + fr, ks + fc, 40);
#pragma unroll
            for (int ni = 0; ni < 8; ni++) {
                uint32_t bb[2];
                LOAD_BFRAG(bb, sB, wn + ni * 8 + fr, ks + fc, 40);
                mma16816(acc[0][ni], a[0], bb);
                mma16816(acc[1][ni], a[1], bb);
            }
        }
    }
    __syncthreads();

    if (mt == 2 || mt == 3) {
        __half* st = (__half*)raw;   // [128 n][136 pitch] staging for transpose
#pragma unroll
        for (int mi = 0; mi < 2; mi++)
#pragma unroll
            for (int ni = 0; ni < 8; ni++)
#pragma unroll
                for (int e = 0; e < 4; e++) {
                    int c = wm + mi * 16 + fr + (e >> 1) * 8;
                    int n = wn + ni * 8 + fc + (e & 1);
                    st[n * 136 + c] = __float2half_rn(phi_f(acc[mi][ni][e]));
                }
        __syncthreads();
        __half* dstb = g_phiKT + ((size_t)b * NHW + nt * 128) * NC + (mt - 2) * 128;
        for (int idx = t; idx < 128 * 16; idx += 256) {
            int nl = idx >> 4, ch = (idx & 15) * 8;
            *(uint4*)&dstb[(size_t)nl * NC + ch] = *(const uint4*)&st[nl * 136 + ch];
        }
    } else {
#pragma unroll
        for (int mi = 0; mi < 2; mi++) {
#pragma unroll
            for (int half = 0; half < 2; half++) {
                int gr = mt * 128 + wm + mi * 16 + fr + half * 8;
                int which = gr >> 8, cc = gr & 255;
                __half* dst = g_phi + (((size_t)b * 3 + which) * NC + cc) * NHW;
#pragma unroll
                for (int ni = 0; ni < 8; ni++) {
                    int gn = nt * 128 + wn + ni * 8 + fc;
                    *(__half2*)&dst[gn] = __floats2half2_rn(
                        phi_f(acc[mi][ni][half * 2 + 0]), phi_f(acc[mi][ni][half * 2 + 1]));
                }
            }
        }
    }
}

// ---------------- K2: qv split-K, 128x64 block / 32x32 warp tile -------------
// grid (dt=4, ct=2, b*4+ks); block 256 = 8 warps (4 m x 2 n). Dynamic smem.
#define QV_SMEM (2 * 27648)
__global__ __launch_bounds__(256) void qv_kernel() {
    extern __shared__ __align__(16) char raw[];     // 2 x (sA 128x72 | sB 64x72)
    const int dt = blockIdx.x, ct = blockIdx.y;
    const int b = blockIdx.z >> 2, ks = blockIdx.z & 3;
    const int t = threadIdx.x, warp = t >> 5, lane = t & 31;
    const int wm = (warp >> 1) * 32, wn = (warp & 1) * 32;
    const int fr = lane >> 2, fc = (lane & 3) * 2;
    const int lr = t >> 3, lc = (t & 7) * 8;

    float acc[2][4][4] = {};
    const __half* Ag = g_phi + (((size_t)b * 3 + 0) * NC + ct * 128) * NHW;
    const __half* Bg = g_phi + (((size_t)b * 3 + 2) * NC + dt * 64) * NHW;
    uint32_t raw_s = (uint32_t)__cvta_generic_to_shared(raw);

    auto issue = [&](int s, int k0) {
        uint32_t base = raw_s + s * 27648;
#pragma unroll
        for (int i = 0; i < 4; i++) {
            int r = lr + i * 32;
            cpa16(base + (r * 72 + lc) * 2, Ag + (size_t)r * NHW + k0 + lc);
        }
#pragma unroll
        for (int i = 0; i < 2; i++) {
            int r = lr + i * 32;
            cpa16(base + 18432 + (r * 72 + lc) * 2, Bg + (size_t)r * NHW + k0 + lc);
        }
    };

    const int kbase = ks * 1024;
    issue(0, kbase); CPA_COMMIT();
    for (int it = 0; it < 16; it++) {
        CPA_WAIT0();
        __syncthreads();
        if (it < 15) { issue((it + 1) & 1, kbase + (it + 1) * 64); CPA_COMMIT(); }
        const __half* sA = (const __half*)(raw + (it & 1) * 27648);
        const __half* sB = sA + 9216;
#pragma unroll
        for (int kk = 0; kk < 64; kk += 16) {
            uint32_t a[2][4];
            LOAD_AFRAG(a[0], sA, wm + fr, kk + fc, 72);
            LOAD_AFRAG(a[1], sA, wm + 16 + fr, kk + fc, 72);
#pragma unroll
            for (int ni = 0; ni < 4; ni++) {
                uint32_t bb[2];
                LOAD_BFRAG(bb, sB, wn + ni * 8 + fr, kk + fc, 72);
                mma16816(acc[0][ni], a[0], bb);
                mma16816(acc[1][ni], a[1], bb);
            }
        }
    }

    float* dst = g_qvp + ((size_t)(ks * NB + b) * NC) * NC;
#pragma unroll
    for (int mi = 0; mi < 2; mi++)
#pragma unroll
        for (int ni = 0; ni < 4; ni++)
#pragma unroll
            for (int half = 0; half < 2; half++) {
                int c = ct * 128 + wm + mi * 16 + fr + half * 8;
                int d = dt * 64 + wn + ni * 8 + fc;
                float2 v;
                v.x = acc[mi][ni][half * 2 + 0];
                v.y = acc[mi][ni][half * 2 + 1];
                *(float2*)&dst[(size_t)c * NC + d] = v;
            }
}

// ---------------- K2.5: M = (Wo * sum_ks qvp)/16, fp16 output ----------------
__global__ __launch_bounds__(256) void mwo_kernel(const float* __restrict__ Wo) {
    __shared__ float sWo[16 * 256];
    const int b = blockIdx.x, o0 = blockIdx.y * 16;
    const int t = threadIdx.x;
#pragma unroll
    for (int i = 0; i < 16; i++)
        sWo[t + i * 256] = Wo[(size_t)(o0 + (t + i * 256) / 256) * NC + ((t + i * 256) & 255)];
    __syncthreads();

    const size_t stride = (size_t)NB * NC * NC;
    const float* q0 = g_qvp + (size_t)b * NC * NC;
    float acc[16] = {};
    for (int c = 0; c < NC; c++) {
        size_t off = (size_t)c * NC + t;
        float q = (q0[off] + q0[stride + off]) + (q0[2 * stride + off] + q0[3 * stride + off]);
#pragma unroll
        for (int o = 0; o < 16; o++) acc[o] = fmaf(sWo[o * 256 + c], q, acc[o]);
    }
#pragma unroll
    for (int o = 0; o < 16; o++)
        g_M[((size_t)b * NC + o0 + o) * NC + t] = __float2half_rn(acc[o] * 0.0625f);
}

// ---------------- K3: out = 16 * (M * phiK^T) + bo (cp.async pipelined) ------
__global__ __launch_bounds__(256) void out_kernel(const float* __restrict__ bo,
                                                  float* __restrict__ out) {
    __shared__ __align__(16) char raw[40960];   // 2 x (sA 128x40 | sB 128x40)
    const int b = blockIdx.z, ot = blockIdx.y, nt = blockIdx.x;
    const int t = threadIdx.x, warp = t >> 5, lane = t & 31;
    const int wm = (warp >> 1) * 32, wn = (warp & 1) * 64;
    const int fr = lane >> 2, fc = (lane & 3) * 2;
    const int lr = t >> 2, lc = (t & 3) * 8;

    float acc[2][8][4] = {};
    const __half* Ag = g_M + ((size_t)b * NC + ot * 128) * NC;
    const __half* Bg = g_phiKT + ((size_t)b * NHW + nt * 128) * NC;
    uint32_t raw_s = (uint32_t)__cvta_generic_to_shared(raw);

    auto issue = [&](int s, int k0) {
        uint32_t base = raw_s + s * 20480;
#pragma unroll
        for (int i = 0; i < 2; i++) {
            int r = lr + i * 64;
            cpa16(base + (r * 40 + lc) * 2, Ag + (size_t)r * NC + k0 + lc);
            cpa16(base + 10240 + (r * 40 + lc) * 2, Bg + (size_t)r * NC + k0 + lc);
        }
    };

    issue(0, 0); CPA_COMMIT();
    for (int it = 0; it < 8; it++) {
        CPA_WAIT0();
        __syncthreads();
        if (it < 7) { issue((it + 1) & 1, (it + 1) * 32); CPA_COMMIT(); }
        const __half* sA = (const __half*)(raw + (it & 1) * 20480);
        const __half* sB = sA + 5120;
#pragma unroll
        for (int ks = 0; ks < 32; ks += 16) {
            uint32_t a[2][4];
            LOAD_AFRAG(a[0], sA, wm + fr, ks + fc, 40);
            LOAD_AFRAG(a[1], sA, wm + 16 + fr, ks + fc, 40);
#pragma unroll
            for (int ni = 0; ni < 8; ni++) {
                uint32_t bb[2];
                LOAD_BFRAG(bb, sB, wn + ni * 8 + fr, ks + fc, 40);
                mma16816(acc[0][ni], a[0], bb);
                mma16816(acc[1][ni], a[1], bb);
            }
        }
    }

#pragma unroll
    for (int mi = 0; mi < 2; mi++)
#pragma unroll
        for (int half = 0; half < 2; half++) {
            int o = ot * 128 + wm + mi * 16 + fr + half * 8;
            float bias = bo[o];
            float* orow = out + ((size_t)b * NC + o) * NHW;
#pragma unroll
            for (int ni = 0; ni < 8; ni++) {
                int gn = nt * 128 + wn + ni * 8 + fc;
                float2 v;
                v.x = acc[mi][ni][half * 2 + 0] * 16.0f + bias;
                v.y = acc[mi][ni][half * 2 + 1] * 16.0f + bias;
                *(float2*)&orow[gn] = v;
            }
        }
}

// ---------------- launch -----------------------------------------------------
extern "C" void kernel_launch(void* const* d_in, const int* in_sizes, int n_in,
                              void* d_out, int out_size) {
    (void)in_sizes; (void)n_in; (void)out_size;
    const float* x  = (const float*)d_in[0];
    const float* Wq = (const float*)d_in[1];
    const float* Wk = (const float*)d_in[2];
    const float* Wv = (const float*)d_in[3];
    const float* Wo = (const float*)d_in[4];
    const float* bo = (const float*)d_in[5];
    float* out = (float*)d_out;

    // Idempotent, capture-safe, no static guard.
    cudaFuncSetAttribute(qv_kernel, cudaFuncAttributeMaxDynamicSharedMemorySize, QV_SMEM);

    prep_weights<<<(NC * NC + 255) / 256, 256>>>(Wq, Wk, Wv);
    transpose_x<<<dim3(NHW / 32, NC / 32, NB), dim3(32, 8)>>>(x);
    proj_kernel<<<dim3(NHW / 128, 768 / 128, NB), 256>>>();
    qv_kernel<<<dim3(NC / 64, NC / 128, NB * 4), 256, QV_SMEM>>>();
    mwo_kernel<<<dim3(NB, 16), 256>>>(Wo);
    out_kernel<<<dim3(NHW / 128, NC / 128, NB), 256>>>(bo, out);
}

// round 13
// speedup vs baseline: 1.1494x; 1.1494x over previous
#include <cuda_runtime.h>
#include <cuda_fp16.h>
#include <cstdint>

#define NB  16
#define NC  256
#define NHW 4096

// ---------------- scratch ----------------------------------------------------
__device__ __half g_Wqkv[3 * NC * NC];
__device__ __half g_xT[(size_t)NB * NHW * NC];        // [b][n][c]
__device__ __half g_phi[(size_t)NB * 3 * NC * NHW];   // [b][q/-/v][c][n] (slot 1 unused)
__device__ __half g_phiKT[(size_t)NB * NHW * NC];     // [b][n][c]
__device__ float  g_qvp[8 * NB * NC * NC];            // split-K partials [ks][b][c][d]
__device__ __half g_M[NB * NC * NC];                  // [b][o][d], scaled by 1/16

// ---------------- helpers ---------------------------------------------------
__device__ __forceinline__ void mma16816(float* c, const uint32_t* a, const uint32_t* b) {
    asm volatile(
        "mma.sync.aligned.m16n8k16.row.col.f32.f16.f16.f32 "
        "{%0,%1,%2,%3},{%4,%5,%6,%7},{%8,%9},{%0,%1,%2,%3};\n"
        : "+f"(c[0]), "+f"(c[1]), "+f"(c[2]), "+f"(c[3])
        : "r"(a[0]), "r"(a[1]), "r"(a[2]), "r"(a[3]), "r"(b[0]), "r"(b[1]));
}
__device__ __forceinline__ float phi_f(float v) { return v > 0.0f ? v + 1.0f : __expf(v); }

__device__ __forceinline__ void cpa16(uint32_t s, const void* g) {
    asm volatile("cp.async.cg.shared.global [%0], [%1], 16;" :: "r"(s), "l"(g));
}
#define CPA_COMMIT() asm volatile("cp.async.commit_group;" ::: "memory")
#define CPA_WAIT0()  asm volatile("cp.async.wait_group 0;" ::: "memory")

#define LOAD_AFRAG(dst, S, r0, kk, P)                                   \
    do {                                                                \
        dst[0] = *(const uint32_t*)&S[(r0) * (P) + (kk)];               \
        dst[1] = *(const uint32_t*)&S[((r0) + 8) * (P) + (kk)];         \
        dst[2] = *(const uint32_t*)&S[(r0) * (P) + (kk) + 8];           \
        dst[3] = *(const uint32_t*)&S[((r0) + 8) * (P) + (kk) + 8];     \
    } while (0)
#define LOAD_BFRAG(dst, S, r0, kk, P)                                   \
    do {                                                                \
        dst[0] = *(const uint32_t*)&S[(r0) * (P) + (kk)];               \
        dst[1] = *(const uint32_t*)&S[(r0) * (P) + (kk) + 8];           \
    } while (0)

// ---------------- K0a: weight prep (fp16 QKV) --------------------------------
__global__ void prep_weights(const float* __restrict__ Wq, const float* __restrict__ Wk,
                             const float* __restrict__ Wv) {
    int i = blockIdx.x * blockDim.x + threadIdx.x;
    if (i < NC * NC) {
        g_Wqkv[i]               = __float2half_rn(Wq[i]);
        g_Wqkv[NC * NC + i]     = __float2half_rn(Wk[i]);
        g_Wqkv[2 * NC * NC + i] = __float2half_rn(Wv[i]);
    }
}

// ---------------- K0b: x[b][c][n] f32 -> g_xT[b][n][c] fp16 ------------------
__global__ void transpose_x(const float* __restrict__ x) {
    __shared__ float tile[32][33];
    int b = blockIdx.z, n0 = blockIdx.x * 32, c0 = blockIdx.y * 32;
    int tx = threadIdx.x, ty = threadIdx.y;
    const float* xb = x + (size_t)b * NC * NHW;
#pragma unroll
    for (int j = 0; j < 32; j += 8)
        tile[ty + j][tx] = xb[(size_t)(c0 + ty + j) * NHW + n0 + tx];
    __syncthreads();
    __half* o = g_xT + (size_t)b * NHW * NC;
#pragma unroll
    for (int j = 0; j < 32; j += 8)
        o[(size_t)(n0 + ty + j) * NC + c0 + tx] = __float2half_rn(tile[tx][ty + j]);
}

// ---------------- K1: QKV projection + phi (cp.async double-buffered) --------
__global__ __launch_bounds__(256) void proj_kernel() {
    __shared__ __align__(16) char raw[40960];
    const int b = blockIdx.z, mt = blockIdx.y, nt = blockIdx.x;
    const int t = threadIdx.x, warp = t >> 5, lane = t & 31;
    const int wm = (warp >> 1) * 32, wn = (warp & 1) * 64;
    const int fr = lane >> 2, fc = (lane & 3) * 2;
    const int lr = t >> 2, lc = (t & 3) * 8;

    float acc[2][8][4] = {};
    const __half* Ag = g_Wqkv + (size_t)(mt * 128) * NC;
    const __half* Bg = g_xT + ((size_t)b * NHW + nt * 128) * NC;
    uint32_t raw_s = (uint32_t)__cvta_generic_to_shared(raw);

    auto issue = [&](int s, int k0) {
        uint32_t base = raw_s + s * 20480;
#pragma unroll
        for (int i = 0; i < 2; i++) {
            int r = lr + i * 64;
            cpa16(base + (r * 40 + lc) * 2, Ag + (size_t)r * NC + k0 + lc);
            cpa16(base + 10240 + (r * 40 + lc) * 2, Bg + (size_t)r * NC + k0 + lc);
        }
    };

    issue(0, 0); CPA_COMMIT();
    for (int it = 0; it < 8; it++) {
        CPA_WAIT0();
        __syncthreads();
        if (it < 7) { issue((it + 1) & 1, (it + 1) * 32); CPA_COMMIT(); }
        const __half* sA = (const __half*)(raw + (it & 1) * 20480);
        const __half* sB = sA + 5120;
#pragma unroll
        for (int ks = 0; ks < 32; ks += 16) {
            uint32_t a[2][4];
            LOAD_AFRAG(a[0], sA, wm + fr, ks + fc, 40);
            LOAD_AFRAG(a[1], sA, wm + 16 + fr, ks + fc, 40);
#pragma unroll
            for (int ni = 0; ni < 8; ni++) {
                uint32_t bb[2];
                LOAD_BFRAG(bb, sB, wn + ni * 8 + fr, ks + fc, 40);
                mma16816(acc[0][ni], a[0], bb);
                mma16816(acc[1][ni], a[1], bb);
            }
        }
    }
    __syncthreads();

    if (mt == 2 || mt == 3) {
        __half* st = (__half*)raw;   // [128 n][136 pitch] staging for transpose
#pragma unroll
        for (int mi = 0; mi < 2; mi++)
#pragma unroll
            for (int ni = 0; ni < 8; ni++)
#pragma unroll
                for (int e = 0; e < 4; e++) {
                    int c = wm + mi * 16 + fr + (e >> 1) * 8;
                    int n = wn + ni * 8 + fc + (e & 1);
                    st[n * 136 + c] = __float2half_rn(phi_f(acc[mi][ni][e]));
                }
        __syncthreads();
        __half* dstb = g_phiKT + ((size_t)b * NHW + nt * 128) * NC + (mt - 2) * 128;
        for (int idx = t; idx < 128 * 16; idx += 256) {
            int nl = idx >> 4, ch = (idx & 15) * 8;
            *(uint4*)&dstb[(size_t)nl * NC + ch] = *(const uint4*)&st[nl * 136 + ch];
        }
    } else {
#pragma unroll
        for (int mi = 0; mi < 2; mi++) {
#pragma unroll
            for (int half = 0; half < 2; half++) {
                int gr = mt * 128 + wm + mi * 16 + fr + half * 8;
                int which = gr >> 8, cc = gr & 255;
                __half* dst = g_phi + (((size_t)b * 3 + which) * NC + cc) * NHW;
#pragma unroll
                for (int ni = 0; ni < 8; ni++) {
                    int gn = nt * 128 + wn + ni * 8 + fc;
                    *(__half2*)&dst[gn] = __floats2half2_rn(
                        phi_f(acc[mi][ni][half * 2 + 0]), phi_f(acc[mi][ni][half * 2 + 1]));
                }
            }
        }
    }
}

// ---------------- K2: qv split-K=8, 128x64 block / 32x32 warp tile -----------
// grid (dt=4, ct=2, b*8+ks); block 256 = 8 warps. Dynamic smem (55 KB).
#define QV_SMEM (2 * 27648)
__global__ __launch_bounds__(256) void qv_kernel() {
    extern __shared__ __align__(16) char raw[];     // 2 x (sA 128x72 | sB 64x72)
    const int dt = blockIdx.x, ct = blockIdx.y;
    const int b = blockIdx.z >> 3, ks = blockIdx.z & 7;
    const int t = threadIdx.x, warp = t >> 5, lane = t & 31;
    const int wm = (warp >> 1) * 32, wn = (warp & 1) * 32;
    const int fr = lane >> 2, fc = (lane & 3) * 2;
    const int lr = t >> 3, lc = (t & 7) * 8;

    float acc[2][4][4] = {};
    const __half* Ag = g_phi + (((size_t)b * 3 + 0) * NC + ct * 128) * NHW;
    const __half* Bg = g_phi + (((size_t)b * 3 + 2) * NC + dt * 64) * NHW;
    uint32_t raw_s = (uint32_t)__cvta_generic_to_shared(raw);

    auto issue = [&](int s, int k0) {
        uint32_t base = raw_s + s * 27648;
#pragma unroll
        for (int i = 0; i < 4; i++) {
            int r = lr + i * 32;
            cpa16(base + (r * 72 + lc) * 2, Ag + (size_t)r * NHW + k0 + lc);
        }
#pragma unroll
        for (int i = 0; i < 2; i++) {
            int r = lr + i * 32;
            cpa16(base + 18432 + (r * 72 + lc) * 2, Bg + (size_t)r * NHW + k0 + lc);
        }
    };

    const int kbase = ks * 512;
    issue(0, kbase); CPA_COMMIT();
    for (int it = 0; it < 8; it++) {
        CPA_WAIT0();
        __syncthreads();
        if (it < 7) { issue((it + 1) & 1, kbase + (it + 1) * 64); CPA_COMMIT(); }
        const __half* sA = (const __half*)(raw + (it & 1) * 27648);
        const __half* sB = sA + 9216;
#pragma unroll
        for (int kk = 0; kk < 64; kk += 16) {
            uint32_t a[2][4];
            LOAD_AFRAG(a[0], sA, wm + fr, kk + fc, 72);
            LOAD_AFRAG(a[1], sA, wm + 16 + fr, kk + fc, 72);
#pragma unroll
            for (int ni = 0; ni < 4; ni++) {
                uint32_t bb[2];
                LOAD_BFRAG(bb, sB, wn + ni * 8 + fr, kk + fc, 72);
                mma16816(acc[0][ni], a[0], bb);
                mma16816(acc[1][ni], a[1], bb);
            }
        }
    }

    float* dst = g_qvp + ((size_t)(ks * NB + b) * NC) * NC;
#pragma unroll
    for (int mi = 0; mi < 2; mi++)
#pragma unroll
        for (int ni = 0; ni < 4; ni++)
#pragma unroll
            for (int half = 0; half < 2; half++) {
                int c = ct * 128 + wm + mi * 16 + fr + half * 8;
                int d = dt * 64 + wn + ni * 8 + fc;
                float2 v;
                v.x = acc[mi][ni][half * 2 + 0];
                v.y = acc[mi][ni][half * 2 + 1];
                *(float2*)&dst[(size_t)c * NC + d] = v;
            }
}

// ---------------- K2.5: M = (Wo * sum_ks qvp)/16, fp16 output ----------------
__global__ __launch_bounds__(256) void mwo_kernel(const float* __restrict__ Wo) {
    __shared__ float sWo[16 * 256];
    const int b = blockIdx.x, o0 = blockIdx.y * 16;
    const int t = threadIdx.x;
#pragma unroll
    for (int i = 0; i < 16; i++)
        sWo[t + i * 256] = Wo[(size_t)(o0 + (t + i * 256) / 256) * NC + ((t + i * 256) & 255)];
    __syncthreads();

    const size_t stride = (size_t)NB * NC * NC;
    const float* q0 = g_qvp + (size_t)b * NC * NC;
    float acc[16] = {};
    for (int c = 0; c < NC; c++) {
        size_t off = (size_t)c * NC + t;
        float q = ((q0[off] + q0[stride + off]) + (q0[2 * stride + off] + q0[3 * stride + off]))
                + ((q0[4 * stride + off] + q0[5 * stride + off]) +
                   (q0[6 * stride + off] + q0[7 * stride + off]));
#pragma unroll
        for (int o = 0; o < 16; o++) acc[o] = fmaf(sWo[o * 256 + c], q, acc[o]);
    }
#pragma unroll
    for (int o = 0; o < 16; o++)
        g_M[((size_t)b * NC + o0 + o) * NC + t] = __float2half_rn(acc[o] * 0.0625f);
}

// ---------------- K3: out = 16 * (M * phiK^T) + bo (cp.async pipelined) ------
__global__ __launch_bounds__(256) void out_kernel(const float* __restrict__ bo,
                                                  float* __restrict__ out) {
    __shared__ __align__(16) char raw[40960];   // 2 x (sA 128x40 | sB 128x40)
    const int b = blockIdx.z, ot = blockIdx.y, nt = blockIdx.x;
    const int t = threadIdx.x, warp = t >> 5, lane = t & 31;
    const int wm = (warp >> 1) * 32, wn = (warp & 1) * 64;
    const int fr = lane >> 2, fc = (lane & 3) * 2;
    const int lr = t >> 2, lc = (t & 3) * 8;

    float acc[2][8][4] = {};
    const __half* Ag = g_M + ((size_t)b * NC + ot * 128) * NC;
    const __half* Bg = g_phiKT + ((size_t)b * NHW + nt * 128) * NC;
    uint32_t raw_s = (uint32_t)__cvta_generic_to_shared(raw);

    auto issue = [&](int s, int k0) {
        uint32_t base = raw_s + s * 20480;
#pragma unroll
        for (int i = 0; i < 2; i++) {
            int r = lr + i * 64;
            cpa16(base + (r * 40 + lc) * 2, Ag + (size_t)r * NC + k0 + lc);
            cpa16(base + 10240 + (r * 40 + lc) * 2, Bg + (size_t)r * NC + k0 + lc);
        }
    };

    issue(0, 0); CPA_COMMIT();
    for (int it = 0; it < 8; it++) {
        CPA_WAIT0();
        __syncthreads();
        if (it < 7) { issue((it + 1) & 1, (it + 1) * 32); CPA_COMMIT(); }
        const __half* sA = (const __half*)(raw + (it & 1) * 20480);
        const __half* sB = sA + 5120;
#pragma unroll
        for (int ks = 0; ks < 32; ks += 16) {
            uint32_t a[2][4];
            LOAD_AFRAG(a[0], sA, wm + fr, ks + fc, 40);
            LOAD_AFRAG(a[1], sA, wm + 16 + fr, ks + fc, 40);
#pragma unroll
            for (int ni = 0; ni < 8; ni++) {
                uint32_t bb[2];
                LOAD_BFRAG(bb, sB, wn + ni * 8 + fr, ks + fc, 40);
                mma16816(acc[0][ni], a[0], bb);
                mma16816(acc[1][ni], a[1], bb);
            }
        }
    }

#pragma unroll
    for (int mi = 0; mi < 2; mi++)
#pragma unroll
        for (int half = 0; half < 2; half++) {
            int o = ot * 128 + wm + mi * 16 + fr + half * 8;
            float bias = bo[o];
            float* orow = out + ((size_t)b * NC + o) * NHW;
#pragma unroll
            for (int ni = 0; ni < 8; ni++) {
                int gn = nt * 128 + wn + ni * 8 + fc;
                float2 v;
                v.x = acc[mi][ni][half * 2 + 0] * 16.0f + bias;
                v.y = acc[mi][ni][half * 2 + 1] * 16.0f + bias;
                *(float2*)&orow[gn] = v;
            }
        }
}

// ---------------- launch -----------------------------------------------------
extern "C" void kernel_launch(void* const* d_in, const int* in_sizes, int n_in,
                              void* d_out, int out_size) {
    (void)in_sizes; (void)n_in; (void)out_size;
    const float* x  = (const float*)d_in[0];
    const float* Wq = (const float*)d_in[1];
    const float* Wk = (const float*)d_in[2];
    const float* Wv = (const float*)d_in[3];
    const float* Wo = (const float*)d_in[4];
    const float* bo = (const float*)d_in[5];
    float* out = (float*)d_out;

    // Idempotent, capture-safe, no static guard.
    cudaFuncSetAttribute(qv_kernel, cudaFuncAttributeMaxDynamicSharedMemorySize, QV_SMEM);

    prep_weights<<<(NC * NC + 255) / 256, 256>>>(Wq, Wk, Wv);
    transpose_x<<<dim3(NHW / 32, NC / 32, NB), dim3(32, 8)>>>(x);
    proj_kernel<<<dim3(NHW / 128, 768 / 128, NB), 256>>>();
    qv_kernel<<<dim3(NC / 64, NC / 128, NB * 8), 256, QV_SMEM>>>();
    mwo_kernel<<<dim3(NB, 16), 256>>>(Wo);
    out_kernel<<<dim3(NHW / 128, NC / 128, NB), 256>>>(bo, out);
}